// round 1
// baseline (speedup 1.0000x reference)
#include <cuda_runtime.h>

#define NNODES 20000
#define DEG 16
#define S 17
#define T 10
#define M 10
#define D 128
#define N_OUTER 5
#define N_SINK 15
#define F1PAD 132   // 128 padded to keep float4 alignment + stagger banks
#define RPAD 12     // 10 padded to 12 (48B rows, float4-aligned)

// Compute tens[m] = constC[s][m] - 2 * sum_v A[s][v]*C2[v][m]
// A[s][v] = sum_{u in mask} P[u][v]   (C1 binary)
__device__ __forceinline__ void compute_tens(const float* Pw, const float* C2w,
                                             const float* c2qw, unsigned msk,
                                             float c1p, float* tens)
{
    float A[M];
#pragma unroll
    for (int m = 0; m < M; m++) A[m] = 0.f;
#pragma unroll
    for (int uu = 0; uu < S; uu++) {
        if ((msk >> uu) & 1u) {
            const float* pr = Pw + uu * RPAD;
            float4 a0 = *(const float4*)(pr);
            float4 a1 = *(const float4*)(pr + 4);
            float2 a2 = *(const float2*)(pr + 8);
            A[0] += a0.x; A[1] += a0.y; A[2] += a0.z; A[3] += a0.w;
            A[4] += a1.x; A[5] += a1.y; A[6] += a1.z; A[7] += a1.w;
            A[8] += a2.x; A[9] += a2.y;
        }
    }
#pragma unroll
    for (int m = 0; m < M; m++) tens[m] = c1p + c2qw[m];
#pragma unroll
    for (int v2 = 0; v2 < M; v2++) {
        float av = -2.f * A[v2];
        const float* c2r = C2w + v2 * RPAD;
#pragma unroll
        for (int m = 0; m < M; m++) tens[m] = fmaf(av, c2r[m], tens[m]);
    }
}

__global__ __launch_bounds__(320, 2)
void ltfgw_kernel(const float* __restrict__ x,
                  const int* __restrict__ edge_dst,     // second row of edge_index
                  const float* __restrict__ C2g,        // templates [T][M][M]
                  const float* __restrict__ F2g,        // templates_features [T][M][D]
                  const float* __restrict__ q0,
                  const float* __restrict__ alpha0,
                  float* __restrict__ out)
{
    __shared__ float    sF1[S][F1PAD];
    __shared__ int      sNodes[S];
    __shared__ unsigned sMask[S];
    __shared__ float    sQ[RPAD];
    __shared__ float    sC2[T][M][RPAD];
    __shared__ float    sC2q[T][RPAD];
    __shared__ float    sNF2[T][RPAD];
    __shared__ float    sP[T][S][RPAD];   // plan
    __shared__ float    sW[T][S][RPAD];   // transpose scratch for g-step
    __shared__ float    sV[T][RPAD];      // v per template

    const int n    = blockIdx.x;
    const int tid  = threadIdx.x;
    const int w    = tid >> 5;      // template index
    const int lane = tid & 31;
    const int s    = lane;
    const bool act = (s < S);

    // ---- setup phase A ----
    if (tid < S) sNodes[tid] = (tid == 0) ? n : edge_dst[n * DEG + tid - 1];
    __syncthreads();

    // cooperative F1 load: 17 rows x 128 floats
    for (int idx = tid; idx < S * 32; idx += 320) {
        int ss = idx >> 5, c = idx & 31;
        float4 v = *(const float4*)(x + (long)sNodes[ss] * D + c * 4);
        *(float4*)&sF1[ss][c * 4] = v;
    }

    if (tid == 0) {
        float qq[M];
        float mx = -1e30f;
#pragma unroll
        for (int m = 0; m < M; m++) { qq[m] = q0[m]; mx = fmaxf(mx, qq[m]); }
        float ssum = 0.f;
#pragma unroll
        for (int m = 0; m < M; m++) { qq[m] = __expf(qq[m] - mx); ssum += qq[m]; }
        float inv = 1.f / ssum;
#pragma unroll
        for (int m = 0; m < M; m++) sQ[m] = qq[m] * inv;
        sQ[10] = 0.f; sQ[11] = 0.f;
    }

    // C1 bitmask (warp 0): match[s1][s2] = any_k(nbr(nodes[s1])[k] == nodes[s2]); symmetrize
    if (w == 0) {
        int nodesr[S];
#pragma unroll
        for (int i = 0; i < S; i++) nodesr[i] = sNodes[i];
        unsigned msk0 = 0;
        if (lane < S) {
            int me = nodesr[lane];
#pragma unroll
            for (int kk = 0; kk < DEG / 4; kk++) {
                int4 nb4 = *(const int4*)(edge_dst + me * DEG + kk * 4);
                int nbs[4] = { nb4.x, nb4.y, nb4.z, nb4.w };
#pragma unroll
                for (int j = 0; j < 4; j++) {
#pragma unroll
                    for (int s2 = 0; s2 < S; s2++)
                        if (nbs[j] == nodesr[s2]) msk0 |= 1u << s2;
                }
            }
        }
        unsigned add = 0;
#pragma unroll
        for (int s2 = 0; s2 < S; s2++) {
            unsigned col = __ballot_sync(0xffffffffu, (msk0 >> s2) & 1u);
            if (lane == s2) add = col;
        }
        msk0 |= add & 0x1FFFFu;
        if (lane < S) sMask[lane] = msk0;
    }

    // per-template: ||F2||^2 per m, and C2 staged into smem
    if (lane < M) {
        const float* f2 = F2g + (w * M + lane) * D;
        float a = 0.f;
#pragma unroll
        for (int c = 0; c < D / 4; c++) {
            float4 v = __ldg((const float4*)(f2 + c * 4));
            a = fmaf(v.x, v.x, fmaf(v.y, v.y, fmaf(v.z, v.z, fmaf(v.w, v.w, a))));
        }
        sNF2[w][lane] = a;
#pragma unroll
        for (int r = 0; r < M; r++)
            sC2[w][r][lane] = __ldg(C2g + (w * M + r) * M + lane);
    }
    __syncthreads();

    // ---- phase B ----
    if (lane < M) {
        float a = 0.f;
#pragma unroll
        for (int b = 0; b < M; b++) {
            float c = sC2[w][lane][b];
            a = fmaf(c * c, sQ[b], a);
        }
        sC2q[w][lane] = a;
    }
    if (lane >= M && lane < RPAD) { sC2q[w][lane] = 0.f; sNF2[w][lane] = 0.f; }

    const float alpha = 1.f / (1.f + __expf(-__ldg(alpha0 + n)));
    const float a1c = 1.f - alpha;
    const float a2c = 2.f * alpha;
    const float p   = act ? (1.f / 17.f) : 0.f;
    const unsigned msk = act ? sMask[s] : 0u;
    const float c1p = act ? (float)__popc(msk) * (1.f / 17.f) : 0.f;
    const float qm  = (lane < M) ? sQ[lane] : 0.f;

    // Mc[s][m] = ||F1[s]||^2 + ||F2[t][m]||^2 - 2 F1[s].F2[t][m]
    float Mc[M];
    {
        float dot[M];
        float nf1 = 0.f;
#pragma unroll
        for (int m = 0; m < M; m++) dot[m] = 0.f;
        const int srow = act ? s : 0;
        const float* f2b = F2g + w * M * D;
#pragma unroll 4
        for (int c = 0; c < D / 4; c++) {
            float4 f1 = *(const float4*)&sF1[srow][c * 4];
            nf1 = fmaf(f1.x, f1.x, fmaf(f1.y, f1.y, fmaf(f1.z, f1.z, fmaf(f1.w, f1.w, nf1))));
#pragma unroll
            for (int m = 0; m < M; m++) {
                float4 f2 = __ldg((const float4*)(f2b + m * D + c * 4));
                dot[m] = fmaf(f1.x, f2.x, fmaf(f1.y, f2.y, fmaf(f1.z, f2.z, fmaf(f1.w, f2.w, dot[m]))));
            }
        }
#pragma unroll
        for (int m = 0; m < M; m++)
            Mc[m] = act ? (nf1 + sNF2[w][m] - 2.f * dot[m]) : 0.f;
    }

    // plan0 = p (x) q
    if (act) {
        float4 qa = *(float4*)&sQ[0];
        float4 qb = *(float4*)&sQ[4];
        float2 qc = *(float2*)&sQ[8];
        *(float4*)&sP[w][s][0] = make_float4(p * qa.x, p * qa.y, p * qa.z, p * qa.w);
        *(float4*)&sP[w][s][4] = make_float4(p * qb.x, p * qb.y, p * qb.z, p * qb.w);
        *(float2*)&sP[w][s][8] = make_float2(p * qc.x, p * qc.y);
    }
    __syncwarp();

    float K[M];
    float u = 0.f;
    float vv[M];
#pragma unroll
    for (int m = 0; m < M; m++) vv[m] = 1.f;

    for (int outer = 0; outer < N_OUTER; outer++) {
        // tens = gw_tens(plan)
        float tens[M];
        compute_tens(&sP[w][0][0], &sC2[w][0][0], &sC2q[w][0], msk, c1p, tens);

        // G, eps, logK, stabilized K = exp(logK - max)
        float G[M];
        float asum = 0.f;
#pragma unroll
        for (int m = 0; m < M; m++) {
            G[m] = act ? (a1c * Mc[m] + a2c * tens[m]) : 0.f;
            asum += fabsf(G[m]);
        }
#pragma unroll
        for (int o = 16; o; o >>= 1) asum += __shfl_xor_sync(0xffffffffu, asum, o);
        float eps = 0.05f * asum * (1.f / 170.f) + 1e-8f;
        float nie = -__fdividef(1.f, eps);
        float mx = -1e30f;
#pragma unroll
        for (int m = 0; m < M; m++) {
            G[m] *= nie;
            if (act) mx = fmaxf(mx, G[m]);
        }
#pragma unroll
        for (int o = 16; o; o >>= 1) mx = fmaxf(mx, __shfl_xor_sync(0xffffffffu, mx, o));
#pragma unroll
        for (int m = 0; m < M; m++) K[m] = act ? __expf(G[m] - mx) : 0.f;

        // Sinkhorn: v = 1; 15x (u-step, v-step); final u-step
        if (lane < RPAD) sV[w][lane] = (lane < M) ? 1.f : 0.f;
        __syncwarp();

        for (int it = 0; it <= N_SINK; it++) {
            float4 va = *(float4*)&sV[w][0];
            float4 vb = *(float4*)&sV[w][4];
            float2 vc = *(float2*)&sV[w][8];
            vv[0] = va.x; vv[1] = va.y; vv[2] = va.z; vv[3] = va.w;
            vv[4] = vb.x; vv[5] = vb.y; vv[6] = vb.z; vv[7] = vb.w;
            vv[8] = vc.x; vv[9] = vc.y;
            float rs = 0.f;
#pragma unroll
            for (int m = 0; m < M; m++) rs = fmaf(K[m], vv[m], rs);
            u = act ? __fdividef(p, fmaxf(rs, 1e-35f)) : 0.f;
            if (it == N_SINK) break;
            if (act) {
                *(float4*)&sW[w][s][0] = make_float4(K[0] * u, K[1] * u, K[2] * u, K[3] * u);
                *(float4*)&sW[w][s][4] = make_float4(K[4] * u, K[5] * u, K[6] * u, K[7] * u);
                *(float2*)&sW[w][s][8] = make_float2(K[8] * u, K[9] * u);
            }
            __syncwarp();
            if (lane < M) {
                float cs = 0.f;
#pragma unroll
                for (int s2 = 0; s2 < S; s2++) cs += sW[w][s2][lane];
                sV[w][lane] = __fdividef(qm, fmaxf(cs, 1e-35f));
            }
            __syncwarp();
        }

        // plan = u (.) K (.) v  -> sP (next outer reads it / final tens reads it)
        if (act) {
            *(float4*)&sP[w][s][0] = make_float4(u * K[0] * vv[0], u * K[1] * vv[1],
                                                 u * K[2] * vv[2], u * K[3] * vv[3]);
            *(float4*)&sP[w][s][4] = make_float4(u * K[4] * vv[4], u * K[5] * vv[5],
                                                 u * K[6] * vv[6], u * K[7] * vv[7]);
            *(float2*)&sP[w][s][8] = make_float2(u * K[8] * vv[8], u * K[9] * vv[9]);
        }
        __syncwarp();
    }

    // final: tens from final plan; lin = <Mc, plan>, gw = <tens, plan>
    float tens[M];
    compute_tens(&sP[w][0][0], &sC2[w][0][0], &sC2q[w][0], msk, c1p, tens);

    float lin = 0.f, gw = 0.f;
#pragma unroll
    for (int m = 0; m < M; m++) {
        float pl = u * K[m] * vv[m];
        lin = fmaf(Mc[m], pl, lin);
        gw  = fmaf(tens[m], pl, gw);
    }
#pragma unroll
    for (int o = 16; o; o >>= 1) {
        lin += __shfl_xor_sync(0xffffffffu, lin, o);
        gw  += __shfl_xor_sync(0xffffffffu, gw, o);
    }
    if (lane == 0)
        out[n * T + w] = a1c * lin + alpha * gw;
}

extern "C" void kernel_launch(void* const* d_in, const int* in_sizes, int n_in,
                              void* d_out, int out_size)
{
    const float* x      = (const float*)d_in[0];
    const int*   ei     = (const int*)d_in[1];
    const float* C2g    = (const float*)d_in[2];
    const float* F2g    = (const float*)d_in[3];
    const float* q0     = (const float*)d_in[4];
    const float* alpha0 = (const float*)d_in[5];
    float* out = (float*)d_out;

    const int* edge_dst = ei + NNODES * DEG;  // second row of edge_index

    ltfgw_kernel<<<NNODES, 320>>>(x, edge_dst, C2g, F2g, q0, alpha0, out);
}

// round 3
// speedup vs baseline: 1.6498x; 1.6498x over previous
#include <cuda_runtime.h>

#define NNODES 20000
#define DEG 16
#define S 17
#define T 10
#define M 10
#define D 128
#define N_OUTER 5
#define N_SINK 15
#define RPAD 12     // 10 padded to 12 (48B rows, float4-aligned)
#define UPAD 20     // 17 padded to 20

// Precomputed scratch: XFP[n][t][m] = ||F2[t][m]||^2 - 2 * x[n].F2[t][m],  NX[n] = ||x[n]||^2
__device__ float g_XFP[(long)NNODES * T * RPAD];
__device__ float g_NX[NNODES];

// ---------------- GEMM precompute kernel ----------------
__global__ __launch_bounds__(128)
void xf2_kernel(const float* __restrict__ x, const float* __restrict__ F2g)
{
    __shared__ float sx[4][D];
    const int tid = threadIdx.x;
    const int nbase = blockIdx.x * 4;
#pragma unroll
    for (int i = 0; i < 4; i++)
        sx[i][tid] = x[(long)(nbase + i) * D + tid];
    __syncthreads();

    if (tid < T * M) {
        const float* f2 = F2g + tid * D;
        float a0 = 0.f, a1 = 0.f, a2 = 0.f, a3 = 0.f, nf = 0.f;
#pragma unroll 8
        for (int c = 0; c < D / 4; c++) {
            float4 f = __ldg((const float4*)(f2 + 4 * c));
            nf = fmaf(f.x, f.x, fmaf(f.y, f.y, fmaf(f.z, f.z, fmaf(f.w, f.w, nf))));
            float4 x0 = *(const float4*)&sx[0][4 * c];
            a0 = fmaf(f.x, x0.x, fmaf(f.y, x0.y, fmaf(f.z, x0.z, fmaf(f.w, x0.w, a0))));
            float4 x1 = *(const float4*)&sx[1][4 * c];
            a1 = fmaf(f.x, x1.x, fmaf(f.y, x1.y, fmaf(f.z, x1.z, fmaf(f.w, x1.w, a1))));
            float4 x2 = *(const float4*)&sx[2][4 * c];
            a2 = fmaf(f.x, x2.x, fmaf(f.y, x2.y, fmaf(f.z, x2.z, fmaf(f.w, x2.w, a2))));
            float4 x3 = *(const float4*)&sx[3][4 * c];
            a3 = fmaf(f.x, x3.x, fmaf(f.y, x3.y, fmaf(f.z, x3.z, fmaf(f.w, x3.w, a3))));
        }
        const int t = tid / M, m = tid % M;
        g_XFP[((long)(nbase + 0) * T + t) * RPAD + m] = nf - 2.f * a0;
        g_XFP[((long)(nbase + 1) * T + t) * RPAD + m] = nf - 2.f * a1;
        g_XFP[((long)(nbase + 2) * T + t) * RPAD + m] = nf - 2.f * a2;
        g_XFP[((long)(nbase + 3) * T + t) * RPAD + m] = nf - 2.f * a3;
    } else if (tid < T * M + 4) {
        const int nn = tid - T * M;
        float a = 0.f;
#pragma unroll 8
        for (int c = 0; c < D / 4; c++) {
            float4 v = *(const float4*)&sx[nn][4 * c];
            a = fmaf(v.x, v.x, fmaf(v.y, v.y, fmaf(v.z, v.z, fmaf(v.w, v.w, a))));
        }
        g_NX[nbase + nn] = a;
    }
}

// tens[m] = c1p + c2q[m] - 2 * sum_v A[v]*C2[v][m],  A[v] = sum_{u in mask} P[u][v]
__device__ __forceinline__ void compute_tens(const float* Pw, const float* C2w,
                                             const float* c2qw, unsigned msk,
                                             float c1p, float* tens)
{
    float A[M];
#pragma unroll
    for (int m = 0; m < M; m++) A[m] = 0.f;
#pragma unroll
    for (int uu = 0; uu < S; uu++) {
        if ((msk >> uu) & 1u) {
            const float* pr = Pw + uu * RPAD;
            float4 a0 = *(const float4*)(pr);
            float4 a1 = *(const float4*)(pr + 4);
            float2 a2 = *(const float2*)(pr + 8);
            A[0] += a0.x; A[1] += a0.y; A[2] += a0.z; A[3] += a0.w;
            A[4] += a1.x; A[5] += a1.y; A[6] += a1.z; A[7] += a1.w;
            A[8] += a2.x; A[9] += a2.y;
        }
    }
#pragma unroll
    for (int m = 0; m < M; m++) tens[m] = c1p + c2qw[m];
#pragma unroll
    for (int v2 = 0; v2 < M; v2++) {
        float av = -2.f * A[v2];
        const float* c2r = C2w + v2 * RPAD;
#pragma unroll
        for (int m = 0; m < M; m++) tens[m] = fmaf(av, c2r[m], tens[m]);
    }
}

__global__ __launch_bounds__(320, 2)
void ltfgw_kernel(const int* __restrict__ edge_dst,
                  const float* __restrict__ C2g,
                  const float* __restrict__ q0,
                  const float* __restrict__ alpha0,
                  float* __restrict__ out)
{
    __shared__ int      sNodes[S];
    __shared__ unsigned sMask[S];
    __shared__ float    sQ[RPAD];
    __shared__ float    sC2[T][M][RPAD];
    __shared__ float    sC2q[T][RPAD];
    __shared__ float    sP[T][S][RPAD];   // plan
    __shared__ float    sW[T][S][RPAD];   // K-transpose scratch (once per outer)
    __shared__ float    sV[T][RPAD];      // v
    __shared__ float    sU[T][UPAD];      // u

    const int n    = blockIdx.x;
    const int tid  = threadIdx.x;
    const int w    = tid >> 5;
    const int lane = tid & 31;
    const int s    = lane;
    const bool act = (s < S);

    if (tid < S) sNodes[tid] = (tid == 0) ? n : edge_dst[n * DEG + tid - 1];
    if (tid == 0) {
        float qq[M];
        float mx = -1e30f;
#pragma unroll
        for (int m = 0; m < M; m++) { qq[m] = q0[m]; mx = fmaxf(mx, qq[m]); }
        float ssum = 0.f;
#pragma unroll
        for (int m = 0; m < M; m++) { qq[m] = __expf(qq[m] - mx); ssum += qq[m]; }
        float inv = 1.f / ssum;
#pragma unroll
        for (int m = 0; m < M; m++) sQ[m] = qq[m] * inv;
        sQ[10] = 0.f; sQ[11] = 0.f;
    }
    __syncthreads();

    // C1 bitmask (warp 0)
    if (w == 0) {
        int nodesr[S];
#pragma unroll
        for (int i = 0; i < S; i++) nodesr[i] = sNodes[i];
        unsigned msk0 = 0;
        if (lane < S) {
            int me = nodesr[lane];
#pragma unroll
            for (int kk = 0; kk < DEG / 4; kk++) {
                int4 nb4 = *(const int4*)(edge_dst + me * DEG + kk * 4);
                int nbs[4] = { nb4.x, nb4.y, nb4.z, nb4.w };
#pragma unroll
                for (int j = 0; j < 4; j++) {
#pragma unroll
                    for (int s2 = 0; s2 < S; s2++)
                        if (nbs[j] == nodesr[s2]) msk0 |= 1u << s2;
                }
            }
        }
        unsigned add = 0;
#pragma unroll
        for (int s2 = 0; s2 < S; s2++) {
            unsigned col = __ballot_sync(0xffffffffu, (msk0 >> s2) & 1u);
            if (lane == s2) add = col;
        }
        msk0 |= add & 0x1FFFFu;
        if (lane < S) sMask[lane] = msk0;
    }

    // C2 staging
    if (lane < M) {
#pragma unroll
        for (int r = 0; r < M; r++)
            sC2[w][r][lane] = __ldg(C2g + (w * M + r) * M + lane);
    }

    // Mc gather from precomputed XFP/NX
    float Mc[M];
    {
        float g[RPAD];
        float nxs = 0.f;
        if (act) {
            const long node = sNodes[s];
            const float* gp = g_XFP + (node * T + w) * RPAD;
            float4 g0 = __ldg((const float4*)(gp));
            float4 g1 = __ldg((const float4*)(gp + 4));
            float2 g2 = __ldg((const float2*)(gp + 8));
            g[0] = g0.x; g[1] = g0.y; g[2] = g0.z; g[3] = g0.w;
            g[4] = g1.x; g[5] = g1.y; g[6] = g1.z; g[7] = g1.w;
            g[8] = g2.x; g[9] = g2.y;
            nxs = __ldg(g_NX + node);
        } else {
#pragma unroll
            for (int m = 0; m < M; m++) g[m] = 0.f;
        }
#pragma unroll
        for (int m = 0; m < M; m++) Mc[m] = act ? (nxs + g[m]) : 0.f;
    }
    __syncthreads();

    // sC2q[m] = sum_b C2[m][b]^2 * q[b]
    if (lane < M) {
        float a = 0.f;
#pragma unroll
        for (int b = 0; b < M; b++) {
            float c = sC2[w][lane][b];
            a = fmaf(c * c, sQ[b], a);
        }
        sC2q[w][lane] = a;
    }
    if (lane >= M && lane < RPAD) sC2q[w][lane] = 0.f;

    const float alpha = 1.f / (1.f + __expf(-__ldg(alpha0 + n)));
    const float a1c = 1.f - alpha;
    const float a2c = 2.f * alpha;
    const float p   = act ? (1.f / 17.f) : 0.f;
    const unsigned msk = act ? sMask[s] : 0u;
    const float c1p = act ? (float)__popc(msk) * (1.f / 17.f) : 0.f;
    const float qm  = (lane < M) ? sQ[lane] : 0.f;

    // plan0 = p (x) q
    if (act) {
        float4 qa = *(float4*)&sQ[0];
        float4 qb = *(float4*)&sQ[4];
        float2 qc = *(float2*)&sQ[8];
        *(float4*)&sP[w][s][0] = make_float4(p * qa.x, p * qa.y, p * qa.z, p * qa.w);
        *(float4*)&sP[w][s][4] = make_float4(p * qb.x, p * qb.y, p * qb.z, p * qb.w);
        *(float2*)&sP[w][s][8] = make_float2(p * qc.x, p * qc.y);
    }
    __syncwarp();

    float K[M];
    float KT[S];
#pragma unroll
    for (int i = 0; i < S; i++) KT[i] = 0.f;
    float u = 0.f;
    float vv[M];
#pragma unroll
    for (int m = 0; m < M; m++) vv[m] = 1.f;

    for (int outer = 0; outer < N_OUTER; outer++) {
        float tens[M];
        compute_tens(&sP[w][0][0], &sC2[w][0][0], &sC2q[w][0], msk, c1p, tens);

        // G, eps, K = exp(-G/eps - max)
        float G[M];
        float asum = 0.f;
#pragma unroll
        for (int m = 0; m < M; m++) {
            G[m] = act ? (a1c * Mc[m] + a2c * tens[m]) : 0.f;
            asum += fabsf(G[m]);
        }
#pragma unroll
        for (int o = 16; o; o >>= 1) asum += __shfl_xor_sync(0xffffffffu, asum, o);
        float eps = 0.05f * asum * (1.f / 170.f) + 1e-8f;
        float nie = -__fdividef(1.f, eps);
        float mx = -1e30f;
#pragma unroll
        for (int m = 0; m < M; m++) {
            G[m] *= nie;
            if (act) mx = fmaxf(mx, G[m]);
        }
#pragma unroll
        for (int o = 16; o; o >>= 1) mx = fmaxf(mx, __shfl_xor_sync(0xffffffffu, mx, o));
#pragma unroll
        for (int m = 0; m < M; m++) K[m] = act ? __expf(G[m] - mx) : 0.f;

        // K transpose -> KT registers in lanes 0..9; init v = 1
        if (act) {
            *(float4*)&sW[w][s][0] = make_float4(K[0], K[1], K[2], K[3]);
            *(float4*)&sW[w][s][4] = make_float4(K[4], K[5], K[6], K[7]);
            *(float2*)&sW[w][s][8] = make_float2(K[8], K[9]);
        }
        __syncwarp();
        if (lane < RPAD) sV[w][lane] = (lane < M) ? 1.f : 0.f;
        if (lane < M) {
#pragma unroll
            for (int s2 = 0; s2 < S; s2++) KT[s2] = sW[w][s2][lane];
        }
        __syncwarp();

        // Sinkhorn
        for (int it = 0; it <= N_SINK; it++) {
            float4 va = *(const float4*)&sV[w][0];
            float4 vb = *(const float4*)&sV[w][4];
            float2 vc = *(const float2*)&sV[w][8];
            vv[0] = va.x; vv[1] = va.y; vv[2] = va.z; vv[3] = va.w;
            vv[4] = vb.x; vv[5] = vb.y; vv[6] = vb.z; vv[7] = vb.w;
            vv[8] = vc.x; vv[9] = vc.y;
            float rs0 = fmaf(K[0], vv[0], fmaf(K[1], vv[1], fmaf(K[2], vv[2], K[3] * vv[3])));
            float rs1 = fmaf(K[4], vv[4], fmaf(K[5], vv[5], fmaf(K[6], vv[6], K[7] * vv[7])));
            float rs2 = fmaf(K[8], vv[8], K[9] * vv[9]);
            float rs = rs0 + rs1 + rs2;
            u = __fdividef(p, fmaxf(rs, 1e-35f));
            if (it == N_SINK) break;
            if (lane < S) sU[w][lane] = u;
            __syncwarp();
            if (lane < M) {
                float4 ua = *(const float4*)&sU[w][0];
                float4 ub = *(const float4*)&sU[w][4];
                float4 uc = *(const float4*)&sU[w][8];
                float4 ud = *(const float4*)&sU[w][12];
                float  ue = sU[w][16];
                float cs0 = fmaf(KT[0], ua.x, fmaf(KT[1], ua.y, fmaf(KT[2], ua.z, KT[3] * ua.w)));
                float cs1 = fmaf(KT[4], ub.x, fmaf(KT[5], ub.y, fmaf(KT[6], ub.z, KT[7] * ub.w)));
                float cs2 = fmaf(KT[8], uc.x, fmaf(KT[9], uc.y, fmaf(KT[10], uc.z, KT[11] * uc.w)));
                float cs3 = fmaf(KT[12], ud.x, fmaf(KT[13], ud.y, fmaf(KT[14], ud.z,
                            fmaf(KT[15], ud.w, KT[16] * ue))));
                float cs = (cs0 + cs1) + (cs2 + cs3);
                sV[w][lane] = __fdividef(qm, fmaxf(cs, 1e-35f));
            }
            __syncwarp();
        }

        // plan = u (.) K (.) v
        if (act) {
            *(float4*)&sP[w][s][0] = make_float4(u * K[0] * vv[0], u * K[1] * vv[1],
                                                 u * K[2] * vv[2], u * K[3] * vv[3]);
            *(float4*)&sP[w][s][4] = make_float4(u * K[4] * vv[4], u * K[5] * vv[5],
                                                 u * K[6] * vv[6], u * K[7] * vv[7]);
            *(float2*)&sP[w][s][8] = make_float2(u * K[8] * vv[8], u * K[9] * vv[9]);
        }
        __syncwarp();
    }

    float tens[M];
    compute_tens(&sP[w][0][0], &sC2[w][0][0], &sC2q[w][0], msk, c1p, tens);

    float lin = 0.f, gw = 0.f;
#pragma unroll
    for (int m = 0; m < M; m++) {
        float pl = u * K[m] * vv[m];
        lin = fmaf(Mc[m], pl, lin);
        gw  = fmaf(tens[m], pl, gw);
    }
#pragma unroll
    for (int o = 16; o; o >>= 1) {
        lin += __shfl_xor_sync(0xffffffffu, lin, o);
        gw  += __shfl_xor_sync(0xffffffffu, gw, o);
    }
    if (lane == 0)
        out[n * T + w] = a1c * lin + alpha * gw;
}

extern "C" void kernel_launch(void* const* d_in, const int* in_sizes, int n_in,
                              void* d_out, int out_size)
{
    const float* x      = (const float*)d_in[0];
    const int*   ei     = (const int*)d_in[1];
    const float* C2g    = (const float*)d_in[2];
    const float* F2g    = (const float*)d_in[3];
    const float* q0     = (const float*)d_in[4];
    const float* alpha0 = (const float*)d_in[5];
    float* out = (float*)d_out;

    const int* edge_dst = ei + NNODES * DEG;

    xf2_kernel<<<NNODES / 4, 128>>>(x, F2g);
    ltfgw_kernel<<<NNODES, 320>>>(edge_dst, C2g, q0, alpha0, out);
}

// round 4
// speedup vs baseline: 1.7129x; 1.0382x over previous
#include <cuda_runtime.h>

#define NNODES 20000
#define DEG 16
#define S 17
#define T 10
#define M 10
#define D 128
#define N_OUTER 5
#define N_SINK 15
#define RPAD 12     // 10 padded to 12 (48B rows, 16B-aligned)
#define UPAD 20     // 17 padded to 20 (80B rows, 16B-aligned)

typedef unsigned long long u64;

// ---- packed f32x2 helpers (sm_100+) ----
__device__ __forceinline__ u64 pk(float lo, float hi) {
    u64 r; asm("mov.b64 %0,{%1,%2};" : "=l"(r) : "f"(lo), "f"(hi)); return r;
}
__device__ __forceinline__ void upk(float& lo, float& hi, u64 v) {
    asm("mov.b64 {%0,%1},%2;" : "=f"(lo), "=f"(hi) : "l"(v));
}
__device__ __forceinline__ u64 f2fma(u64 a, u64 b, u64 c) {
    u64 d; asm("fma.rn.f32x2 %0,%1,%2,%3;" : "=l"(d) : "l"(a), "l"(b), "l"(c)); return d;
}
__device__ __forceinline__ u64 f2mul(u64 a, u64 b) {
    u64 d; asm("mul.rn.f32x2 %0,%1,%2;" : "=l"(d) : "l"(a), "l"(b)); return d;
}
__device__ __forceinline__ u64 f2add(u64 a, u64 b) {
    u64 d; asm("add.rn.f32x2 %0,%1,%2;" : "=l"(d) : "l"(a), "l"(b)); return d;
}

// Precomputed: XFP[n][t][m] = ||F2[t][m]||^2 - 2 x[n].F2[t][m],  NX[n] = ||x[n]||^2
__device__ float g_XFP[(long)NNODES * T * RPAD];
__device__ float g_NX[NNODES];

__global__ __launch_bounds__(128)
void xf2_kernel(const float* __restrict__ x, const float* __restrict__ F2g)
{
    __shared__ float sx[4][D];
    const int tid = threadIdx.x;
    const int nbase = blockIdx.x * 4;
#pragma unroll
    for (int i = 0; i < 4; i++)
        sx[i][tid] = x[(long)(nbase + i) * D + tid];
    __syncthreads();

    if (tid < T * M) {
        const float* f2 = F2g + tid * D;
        float a0 = 0.f, a1 = 0.f, a2 = 0.f, a3 = 0.f, nf = 0.f;
#pragma unroll 8
        for (int c = 0; c < D / 4; c++) {
            float4 f = __ldg((const float4*)(f2 + 4 * c));
            nf = fmaf(f.x, f.x, fmaf(f.y, f.y, fmaf(f.z, f.z, fmaf(f.w, f.w, nf))));
            float4 x0 = *(const float4*)&sx[0][4 * c];
            a0 = fmaf(f.x, x0.x, fmaf(f.y, x0.y, fmaf(f.z, x0.z, fmaf(f.w, x0.w, a0))));
            float4 x1 = *(const float4*)&sx[1][4 * c];
            a1 = fmaf(f.x, x1.x, fmaf(f.y, x1.y, fmaf(f.z, x1.z, fmaf(f.w, x1.w, a1))));
            float4 x2 = *(const float4*)&sx[2][4 * c];
            a2 = fmaf(f.x, x2.x, fmaf(f.y, x2.y, fmaf(f.z, x2.z, fmaf(f.w, x2.w, a2))));
            float4 x3 = *(const float4*)&sx[3][4 * c];
            a3 = fmaf(f.x, x3.x, fmaf(f.y, x3.y, fmaf(f.z, x3.z, fmaf(f.w, x3.w, a3))));
        }
        const int t = tid / M, m = tid % M;
        g_XFP[((long)(nbase + 0) * T + t) * RPAD + m] = nf - 2.f * a0;
        g_XFP[((long)(nbase + 1) * T + t) * RPAD + m] = nf - 2.f * a1;
        g_XFP[((long)(nbase + 2) * T + t) * RPAD + m] = nf - 2.f * a2;
        g_XFP[((long)(nbase + 3) * T + t) * RPAD + m] = nf - 2.f * a3;
    } else if (tid < T * M + 4) {
        const int nn = tid - T * M;
        float a = 0.f;
#pragma unroll 8
        for (int c = 0; c < D / 4; c++) {
            float4 v = *(const float4*)&sx[nn][4 * c];
            a = fmaf(v.x, v.x, fmaf(v.y, v.y, fmaf(v.z, v.z, fmaf(v.w, v.w, a))));
        }
        g_NX[nbase + nn] = a;
    }
}

// tens2[j] (packed pairs over m) = c1p + c2q[m] - 2 * sum_v A[v]*C2[v][m]
// A[v] = sum_{u in mask} P[u][v]
__device__ __forceinline__ void compute_tens2(const float* Pw, const float* C2w,
                                              const float* c2qw, unsigned msk,
                                              u64 c1p2, u64* tens2)
{
    u64 A0 = 0, A1 = 0, A2v = 0, A3 = 0, A4 = 0;
#pragma unroll
    for (int uu = 0; uu < S; uu++) {
        const float* pr = Pw + uu * RPAD;
        ulonglong2 r01 = *(const ulonglong2*)pr;
        ulonglong2 r23 = *(const ulonglong2*)(pr + 4);
        u64 r4 = *(const u64*)(pr + 8);
        unsigned bit = (msk >> uu) & 1u;
        asm("{\n\t.reg .pred p;\n\t"
            "setp.ne.u32 p,%5,0;\n\t"
            "@p add.rn.f32x2 %0,%0,%6;\n\t"
            "@p add.rn.f32x2 %1,%1,%7;\n\t"
            "@p add.rn.f32x2 %2,%2,%8;\n\t"
            "@p add.rn.f32x2 %3,%3,%9;\n\t"
            "@p add.rn.f32x2 %4,%4,%10;\n\t}"
            : "+l"(A0), "+l"(A1), "+l"(A2v), "+l"(A3), "+l"(A4)
            : "r"(bit), "l"(r01.x), "l"(r01.y), "l"(r23.x), "l"(r23.y), "l"(r4));
    }
    {
        ulonglong2 cq01 = *(const ulonglong2*)c2qw;
        ulonglong2 cq23 = *(const ulonglong2*)(c2qw + 4);
        u64 cq4 = *(const u64*)(c2qw + 8);
        tens2[0] = f2add(c1p2, cq01.x);
        tens2[1] = f2add(c1p2, cq01.y);
        tens2[2] = f2add(c1p2, cq23.x);
        tens2[3] = f2add(c1p2, cq23.y);
        tens2[4] = f2add(c1p2, cq4);
    }
    float a[M];
    upk(a[0], a[1], A0); upk(a[2], a[3], A1); upk(a[4], a[5], A2v);
    upk(a[6], a[7], A3); upk(a[8], a[9], A4);
#pragma unroll
    for (int v = 0; v < M; v++) {
        float av = -2.f * a[v];
        u64 av2 = pk(av, av);
        const float* c2r = C2w + v * RPAD;
        ulonglong2 c01 = *(const ulonglong2*)c2r;
        ulonglong2 c23 = *(const ulonglong2*)(c2r + 4);
        u64 c4 = *(const u64*)(c2r + 8);
        tens2[0] = f2fma(av2, c01.x, tens2[0]);
        tens2[1] = f2fma(av2, c01.y, tens2[1]);
        tens2[2] = f2fma(av2, c23.x, tens2[2]);
        tens2[3] = f2fma(av2, c23.y, tens2[3]);
        tens2[4] = f2fma(av2, c4,    tens2[4]);
    }
}

__global__ __launch_bounds__(320, 2)
void ltfgw_kernel(const int* __restrict__ edge_dst,
                  const float* __restrict__ C2g,
                  const float* __restrict__ q0,
                  const float* __restrict__ alpha0,
                  float* __restrict__ out)
{
    __shared__ __align__(16) int      sNodes[S];
    __shared__ __align__(16) unsigned sMask[S];
    __shared__ __align__(16) float    sQ[RPAD];
    __shared__ __align__(16) float    sC2[T][M][RPAD];
    __shared__ __align__(16) float    sC2q[T][RPAD];
    __shared__ __align__(16) float    sP[T][S][RPAD];   // plan
    __shared__ __align__(16) float    sW[T][S][RPAD];   // K rows (for KT gather)
    __shared__ __align__(16) float    sV[T][RPAD];      // v
    __shared__ __align__(16) float    sU[T][UPAD];      // u

    const int n    = blockIdx.x;
    const int tid  = threadIdx.x;
    const int w    = tid >> 5;
    const int lane = tid & 31;
    const int s    = lane;
    const bool act = (s < S);

    if (tid < S) sNodes[tid] = (tid == 0) ? n : edge_dst[n * DEG + tid - 1];
    if (tid == 0) {
        float qq[M];
        float mxq = -1e30f;
#pragma unroll
        for (int m = 0; m < M; m++) { qq[m] = q0[m]; mxq = fmaxf(mxq, qq[m]); }
        float ssum = 0.f;
#pragma unroll
        for (int m = 0; m < M; m++) { qq[m] = __expf(qq[m] - mxq); ssum += qq[m]; }
        float inv = 1.f / ssum;
#pragma unroll
        for (int m = 0; m < M; m++) sQ[m] = qq[m] * inv;
        sQ[10] = 0.f; sQ[11] = 0.f;
    }
    __syncthreads();

    // C1 bitmask (warp 0)
    if (w == 0) {
        int nodesr[S];
#pragma unroll
        for (int i = 0; i < S; i++) nodesr[i] = sNodes[i];
        unsigned msk0 = 0;
        if (lane < S) {
            int me = nodesr[lane];
#pragma unroll
            for (int kk = 0; kk < DEG / 4; kk++) {
                int4 nb4 = *(const int4*)(edge_dst + me * DEG + kk * 4);
                int nbs[4] = { nb4.x, nb4.y, nb4.z, nb4.w };
#pragma unroll
                for (int j = 0; j < 4; j++) {
#pragma unroll
                    for (int s2 = 0; s2 < S; s2++)
                        if (nbs[j] == nodesr[s2]) msk0 |= 1u << s2;
                }
            }
        }
        unsigned add = 0;
#pragma unroll
        for (int s2 = 0; s2 < S; s2++) {
            unsigned col = __ballot_sync(0xffffffffu, (msk0 >> s2) & 1u);
            if (lane == s2) add = col;
        }
        msk0 |= add & 0x1FFFFu;
        if (lane < S) sMask[lane] = msk0;
    }

    // C2 staging
    if (lane < M) {
#pragma unroll
        for (int r = 0; r < M; r++)
            sC2[w][r][lane] = __ldg(C2g + (w * M + r) * M + lane);
    }

    // Mc gather (packed)
    u64 Mc2[5];
    {
        if (act) {
            const long node = sNodes[s];
            const float* gp = g_XFP + (node * T + w) * RPAD;
            ulonglong2 g01 = __ldg((const ulonglong2*)gp);
            ulonglong2 g23 = __ldg((const ulonglong2*)(gp + 4));
            u64 g4 = __ldg((const u64*)(gp + 8));
            float nxs = __ldg(g_NX + node);
            u64 nx2 = pk(nxs, nxs);
            Mc2[0] = f2add(nx2, g01.x);
            Mc2[1] = f2add(nx2, g01.y);
            Mc2[2] = f2add(nx2, g23.x);
            Mc2[3] = f2add(nx2, g23.y);
            Mc2[4] = f2add(nx2, g4);
        } else {
#pragma unroll
            for (int j = 0; j < 5; j++) Mc2[j] = 0;
        }
    }
    __syncthreads();

    // sC2q[m] = sum_b C2[m][b]^2 * q[b]
    if (lane < M) {
        float a = 0.f;
#pragma unroll
        for (int b = 0; b < M; b++) {
            float c = sC2[w][lane][b];
            a = fmaf(c * c, sQ[b], a);
        }
        sC2q[w][lane] = a;
    }
    if (lane >= M && lane < RPAD) sC2q[w][lane] = 0.f;

    const float alpha = 1.f / (1.f + __expf(-__ldg(alpha0 + n)));
    const float a1c = 1.f - alpha;
    const float a2c = 2.f * alpha;
    const u64 a1c2 = pk(a1c, a1c);
    const u64 a2c2 = pk(a2c, a2c);
    const float p   = act ? (1.f / 17.f) : 0.f;
    const unsigned msk = act ? sMask[s] : 0u;
    const float c1p = act ? (float)__popc(msk) * (1.f / 17.f) : 0.f;
    const u64 c1p2 = pk(c1p, c1p);
    const float qm  = (lane < M) ? sQ[lane] : 0.f;

    // plan0 = p (x) q  (packed)
    if (act) {
        ulonglong2 qa = *(const ulonglong2*)&sQ[0];
        u64 qc = *(const u64*)&sQ[8];
        u64 p2 = pk(p, p);
        ulonglong2 o01; o01.x = f2mul(p2, qa.x); o01.y = f2mul(p2, qa.y);
        *(ulonglong2*)&sP[w][s][0] = o01;
        ulonglong2 qb = *(const ulonglong2*)&sQ[4];
        ulonglong2 o23; o23.x = f2mul(p2, qb.x); o23.y = f2mul(p2, qb.y);
        *(ulonglong2*)&sP[w][s][4] = o23;
        *(u64*)&sP[w][s][8] = f2mul(p2, qc);
    }
    __syncwarp();

    u64 K2[5];
    u64 KT2[8];
    float KT16 = 0.f;
#pragma unroll
    for (int j = 0; j < 8; j++) KT2[j] = 0;
#pragma unroll
    for (int j = 0; j < 5; j++) K2[j] = 0;
    u64 v2r[5];
    float u = 0.f;

    for (int outer = 0; outer < N_OUTER; outer++) {
        u64 tens2[5];
        compute_tens2(&sP[w][0][0], &sC2[w][0][0], &sC2q[w][0], msk, c1p2, tens2);

        // G = a1c*Mc + a2c*tens (packed), eps from warp-mean |G|, K = exp(G*nie - mx)
        float Gs[M];
        {
            u64 G2;
            G2 = f2fma(a2c2, tens2[0], f2mul(a1c2, Mc2[0])); upk(Gs[0], Gs[1], G2);
            G2 = f2fma(a2c2, tens2[1], f2mul(a1c2, Mc2[1])); upk(Gs[2], Gs[3], G2);
            G2 = f2fma(a2c2, tens2[2], f2mul(a1c2, Mc2[2])); upk(Gs[4], Gs[5], G2);
            G2 = f2fma(a2c2, tens2[3], f2mul(a1c2, Mc2[3])); upk(Gs[6], Gs[7], G2);
            G2 = f2fma(a2c2, tens2[4], f2mul(a1c2, Mc2[4])); upk(Gs[8], Gs[9], G2);
        }
        float asum = 0.f;
#pragma unroll
        for (int m = 0; m < M; m++) asum += fabsf(Gs[m]);
        asum = act ? asum : 0.f;
#pragma unroll
        for (int o = 16; o; o >>= 1) asum += __shfl_xor_sync(0xffffffffu, asum, o);
        float eps = 0.05f * asum * (1.f / 170.f) + 1e-8f;
        float nie = -__fdividef(1.f, eps);
        float mx = -1e30f;
#pragma unroll
        for (int m = 0; m < M; m++) {
            Gs[m] *= nie;
            if (act) mx = fmaxf(mx, Gs[m]);
        }
#pragma unroll
        for (int o = 16; o; o >>= 1) mx = fmaxf(mx, __shfl_xor_sync(0xffffffffu, mx, o));
        float Ks[M];
#pragma unroll
        for (int m = 0; m < M; m++) Ks[m] = act ? __expf(Gs[m] - mx) : 0.f;
#pragma unroll
        for (int j = 0; j < 5; j++) K2[j] = pk(Ks[2 * j], Ks[2 * j + 1]);

        // K rows -> sW; gather KT columns (lanes 0..9); v = 1
        if (act) {
            ulonglong2 o01; o01.x = K2[0]; o01.y = K2[1];
            *(ulonglong2*)&sW[w][s][0] = o01;
            ulonglong2 o23; o23.x = K2[2]; o23.y = K2[3];
            *(ulonglong2*)&sW[w][s][4] = o23;
            *(u64*)&sW[w][s][8] = K2[4];
        }
        __syncwarp();
        if (lane < RPAD) sV[w][lane] = (lane < M) ? 1.f : 0.f;
        if (lane < M) {
            float kt[S];
#pragma unroll
            for (int s2 = 0; s2 < S; s2++) kt[s2] = sW[w][s2][lane];
#pragma unroll
            for (int j = 0; j < 8; j++) KT2[j] = pk(kt[2 * j], kt[2 * j + 1]);
            KT16 = kt[16];
        }
        __syncwarp();

        // Sinkhorn
        for (int it = 0; it <= N_SINK; it++) {
            ulonglong2 va = *(const ulonglong2*)&sV[w][0];
            ulonglong2 vb = *(const ulonglong2*)&sV[w][4];
            u64 vc = *(const u64*)&sV[w][8];
            v2r[0] = va.x; v2r[1] = va.y; v2r[2] = vb.x; v2r[3] = vb.y; v2r[4] = vc;
            u64 acc = f2mul(K2[0], v2r[0]);
            acc = f2fma(K2[1], v2r[1], acc);
            acc = f2fma(K2[2], v2r[2], acc);
            acc = f2fma(K2[3], v2r[3], acc);
            acc = f2fma(K2[4], v2r[4], acc);
            float lo, hi; upk(lo, hi, acc);
            float rs = lo + hi;
            u = __fdividef(p, fmaxf(rs, 1e-35f));
            if (it == N_SINK) break;
            if (lane < S) sU[w][lane] = u;
            __syncwarp();
            if (lane < M) {
                ulonglong2 ua = *(const ulonglong2*)&sU[w][0];
                ulonglong2 ub = *(const ulonglong2*)&sU[w][4];
                ulonglong2 uc = *(const ulonglong2*)&sU[w][8];
                ulonglong2 ud = *(const ulonglong2*)&sU[w][12];
                float ue = sU[w][16];
                u64 a2 = f2mul(KT2[0], ua.x);
                a2 = f2fma(KT2[1], ua.y, a2);
                a2 = f2fma(KT2[2], ub.x, a2);
                a2 = f2fma(KT2[3], ub.y, a2);
                a2 = f2fma(KT2[4], uc.x, a2);
                a2 = f2fma(KT2[5], uc.y, a2);
                a2 = f2fma(KT2[6], ud.x, a2);
                a2 = f2fma(KT2[7], ud.y, a2);
                float clo, chi; upk(clo, chi, a2);
                float cs = (clo + chi) + KT16 * ue;
                sV[w][lane] = __fdividef(qm, fmaxf(cs, 1e-35f));
            }
            __syncwarp();
        }

        // plan = u (.) K (.) v  (packed)
        if (act) {
            u64 uu2 = pk(u, u);
            ulonglong2 o01;
            o01.x = f2mul(f2mul(uu2, K2[0]), v2r[0]);
            o01.y = f2mul(f2mul(uu2, K2[1]), v2r[1]);
            *(ulonglong2*)&sP[w][s][0] = o01;
            ulonglong2 o23;
            o23.x = f2mul(f2mul(uu2, K2[2]), v2r[2]);
            o23.y = f2mul(f2mul(uu2, K2[3]), v2r[3]);
            *(ulonglong2*)&sP[w][s][4] = o23;
            *(u64*)&sP[w][s][8] = f2mul(f2mul(uu2, K2[4]), v2r[4]);
        }
        __syncwarp();
    }

    // final tens + contractions
    u64 tens2[5];
    compute_tens2(&sP[w][0][0], &sC2[w][0][0], &sC2q[w][0], msk, c1p2, tens2);

    u64 lin2 = 0, gw2 = 0;
    {
        u64 uu2 = pk(u, u);
#pragma unroll
        for (int j = 0; j < 5; j++) {
            u64 pl2 = f2mul(f2mul(uu2, K2[j]), v2r[j]);
            lin2 = f2fma(Mc2[j], pl2, lin2);
            gw2  = f2fma(tens2[j], pl2, gw2);
        }
    }
    float llo, lhi, glo, ghi;
    upk(llo, lhi, lin2);
    upk(glo, ghi, gw2);
    float lin = llo + lhi, gw = glo + ghi;
#pragma unroll
    for (int o = 16; o; o >>= 1) {
        lin += __shfl_xor_sync(0xffffffffu, lin, o);
        gw  += __shfl_xor_sync(0xffffffffu, gw, o);
    }
    if (lane == 0)
        out[n * T + w] = a1c * lin + alpha * gw;
}

extern "C" void kernel_launch(void* const* d_in, const int* in_sizes, int n_in,
                              void* d_out, int out_size)
{
    const float* x      = (const float*)d_in[0];
    const int*   ei     = (const int*)d_in[1];
    const float* C2g    = (const float*)d_in[2];
    const float* F2g    = (const float*)d_in[3];
    const float* q0     = (const float*)d_in[4];
    const float* alpha0 = (const float*)d_in[5];
    float* out = (float*)d_out;

    const int* edge_dst = ei + NNODES * DEG;

    xf2_kernel<<<NNODES / 4, 128>>>(x, F2g);
    ltfgw_kernel<<<NNODES, 320>>>(edge_dst, C2g, q0, alpha0, out);
}

// round 6
// speedup vs baseline: 1.9123x; 1.1164x over previous
#include <cuda_runtime.h>

#define NNODES 20000
#define DEG 16
#define S 17
#define T 10
#define M 10
#define D 128
#define N_OUTER 5
#define N_SINK 15
#define RPAD 12     // 10 padded to 12 (48B rows, 16B-aligned)
#define UPAD 20     // 18 padded to 20 (80B rows, 16B-aligned)

typedef unsigned long long u64;

// ---- packed f32x2 helpers (sm_100+) ----
__device__ __forceinline__ u64 pk(float lo, float hi) {
    u64 r; asm("mov.b64 %0,{%1,%2};" : "=l"(r) : "f"(lo), "f"(hi)); return r;
}
__device__ __forceinline__ void upk(float& lo, float& hi, u64 v) {
    asm("mov.b64 {%0,%1},%2;" : "=f"(lo), "=f"(hi) : "l"(v));
}
__device__ __forceinline__ u64 f2fma(u64 a, u64 b, u64 c) {
    u64 d; asm("fma.rn.f32x2 %0,%1,%2,%3;" : "=l"(d) : "l"(a), "l"(b), "l"(c)); return d;
}
__device__ __forceinline__ u64 f2mul(u64 a, u64 b) {
    u64 d; asm("mul.rn.f32x2 %0,%1,%2;" : "=l"(d) : "l"(a), "l"(b)); return d;
}
__device__ __forceinline__ u64 f2add(u64 a, u64 b) {
    u64 d; asm("add.rn.f32x2 %0,%1,%2;" : "=l"(d) : "l"(a), "l"(b)); return d;
}

// Precomputed: XFP[n][t][m] = ||F2[t][m]||^2 - 2 x[n].F2[t][m],  NX[n] = ||x[n]||^2
__device__ float g_XFP[(long)NNODES * T * RPAD];
__device__ float g_NX[NNODES];

__global__ __launch_bounds__(128)
void xf2_kernel(const float* __restrict__ x, const float* __restrict__ F2g)
{
    __shared__ float sx[4][D];
    const int tid = threadIdx.x;
    const int nbase = blockIdx.x * 4;
#pragma unroll
    for (int i = 0; i < 4; i++)
        sx[i][tid] = x[(long)(nbase + i) * D + tid];
    __syncthreads();

    if (tid < T * M) {
        const float* f2 = F2g + tid * D;
        float a0 = 0.f, a1 = 0.f, a2 = 0.f, a3 = 0.f, nf = 0.f;
#pragma unroll 8
        for (int c = 0; c < D / 4; c++) {
            float4 f = __ldg((const float4*)(f2 + 4 * c));
            nf = fmaf(f.x, f.x, fmaf(f.y, f.y, fmaf(f.z, f.z, fmaf(f.w, f.w, nf))));
            float4 x0 = *(const float4*)&sx[0][4 * c];
            a0 = fmaf(f.x, x0.x, fmaf(f.y, x0.y, fmaf(f.z, x0.z, fmaf(f.w, x0.w, a0))));
            float4 x1 = *(const float4*)&sx[1][4 * c];
            a1 = fmaf(f.x, x1.x, fmaf(f.y, x1.y, fmaf(f.z, x1.z, fmaf(f.w, x1.w, a1))));
            float4 x2 = *(const float4*)&sx[2][4 * c];
            a2 = fmaf(f.x, x2.x, fmaf(f.y, x2.y, fmaf(f.z, x2.z, fmaf(f.w, x2.w, a2))));
            float4 x3 = *(const float4*)&sx[3][4 * c];
            a3 = fmaf(f.x, x3.x, fmaf(f.y, x3.y, fmaf(f.z, x3.z, fmaf(f.w, x3.w, a3))));
        }
        const int t = tid / M, m = tid % M;
        g_XFP[((long)(nbase + 0) * T + t) * RPAD + m] = nf - 2.f * a0;
        g_XFP[((long)(nbase + 1) * T + t) * RPAD + m] = nf - 2.f * a1;
        g_XFP[((long)(nbase + 2) * T + t) * RPAD + m] = nf - 2.f * a2;
        g_XFP[((long)(nbase + 3) * T + t) * RPAD + m] = nf - 2.f * a3;
    } else if (tid < T * M + 4) {
        const int nn = tid - T * M;
        float a = 0.f;
#pragma unroll 8
        for (int c = 0; c < D / 4; c++) {
            float4 v = *(const float4*)&sx[nn][4 * c];
            a = fmaf(v.x, v.x, fmaf(v.y, v.y, fmaf(v.z, v.z, fmaf(v.w, v.w, a))));
        }
        g_NX[nbase + nn] = a;
    }
}

// Fused tens for TWO rows (ra, rb) of the same template:
// tens[r][m] = c1p[r] + c2q[m] - 2 sum_v A[r][v] C2[v][m],  A[r][v] = sum_{u in mask_r} P[u][v]
__device__ __forceinline__ void tens_pair(const float* Pw, const float* C2w,
                                          const float* c2qw,
                                          unsigned mka, unsigned mkb,
                                          u64 c1pa2, u64 c1pb2,
                                          u64* ta, u64* tb)
{
    u64 Aa0 = 0, Aa1 = 0, Aa2 = 0, Aa3 = 0, Aa4 = 0;
    u64 Ab0 = 0, Ab1 = 0, Ab2 = 0, Ab3 = 0, Ab4 = 0;
#pragma unroll
    for (int uu = 0; uu < S; uu++) {
        const float* pr = Pw + uu * RPAD;
        ulonglong2 r01 = *(const ulonglong2*)pr;
        ulonglong2 r23 = *(const ulonglong2*)(pr + 4);
        u64 r4 = *(const u64*)(pr + 8);
        unsigned ba = (mka >> uu) & 1u;
        unsigned bb = (mkb >> uu) & 1u;
        asm("{\n\t.reg .pred pa,pb;\n\t"
            "setp.ne.u32 pa,%10,0;\n\t"
            "setp.ne.u32 pb,%11,0;\n\t"
            "@pa add.rn.f32x2 %0,%0,%12;\n\t"
            "@pa add.rn.f32x2 %1,%1,%13;\n\t"
            "@pa add.rn.f32x2 %2,%2,%14;\n\t"
            "@pa add.rn.f32x2 %3,%3,%15;\n\t"
            "@pa add.rn.f32x2 %4,%4,%16;\n\t"
            "@pb add.rn.f32x2 %5,%5,%12;\n\t"
            "@pb add.rn.f32x2 %6,%6,%13;\n\t"
            "@pb add.rn.f32x2 %7,%7,%14;\n\t"
            "@pb add.rn.f32x2 %8,%8,%15;\n\t"
            "@pb add.rn.f32x2 %9,%9,%16;\n\t}"
            : "+l"(Aa0), "+l"(Aa1), "+l"(Aa2), "+l"(Aa3), "+l"(Aa4),
              "+l"(Ab0), "+l"(Ab1), "+l"(Ab2), "+l"(Ab3), "+l"(Ab4)
            : "r"(ba), "r"(bb),
              "l"(r01.x), "l"(r01.y), "l"(r23.x), "l"(r23.y), "l"(r4));
    }
    {
        ulonglong2 cq01 = *(const ulonglong2*)c2qw;
        ulonglong2 cq23 = *(const ulonglong2*)(c2qw + 4);
        u64 cq4 = *(const u64*)(c2qw + 8);
        ta[0] = f2add(c1pa2, cq01.x); tb[0] = f2add(c1pb2, cq01.x);
        ta[1] = f2add(c1pa2, cq01.y); tb[1] = f2add(c1pb2, cq01.y);
        ta[2] = f2add(c1pa2, cq23.x); tb[2] = f2add(c1pb2, cq23.x);
        ta[3] = f2add(c1pa2, cq23.y); tb[3] = f2add(c1pb2, cq23.y);
        ta[4] = f2add(c1pa2, cq4);    tb[4] = f2add(c1pb2, cq4);
    }
    float aav[M], abv[M];
    upk(aav[0], aav[1], Aa0); upk(aav[2], aav[3], Aa1); upk(aav[4], aav[5], Aa2);
    upk(aav[6], aav[7], Aa3); upk(aav[8], aav[9], Aa4);
    upk(abv[0], abv[1], Ab0); upk(abv[2], abv[3], Ab1); upk(abv[4], abv[5], Ab2);
    upk(abv[6], abv[7], Ab3); upk(abv[8], abv[9], Ab4);
#pragma unroll
    for (int v = 0; v < M; v++) {
        u64 ava2 = pk(-2.f * aav[v], -2.f * aav[v]);
        u64 avb2 = pk(-2.f * abv[v], -2.f * abv[v]);
        const float* c2r = C2w + v * RPAD;
        ulonglong2 c01 = *(const ulonglong2*)c2r;
        ulonglong2 c23 = *(const ulonglong2*)(c2r + 4);
        u64 c4 = *(const u64*)(c2r + 8);
        ta[0] = f2fma(ava2, c01.x, ta[0]); tb[0] = f2fma(avb2, c01.x, tb[0]);
        ta[1] = f2fma(ava2, c01.y, ta[1]); tb[1] = f2fma(avb2, c01.y, tb[1]);
        ta[2] = f2fma(ava2, c23.x, ta[2]); tb[2] = f2fma(avb2, c23.x, tb[2]);
        ta[3] = f2fma(ava2, c23.y, ta[3]); tb[3] = f2fma(avb2, c23.y, tb[3]);
        ta[4] = f2fma(ava2, c4,    ta[4]); tb[4] = f2fma(avb2, c4,    tb[4]);
    }
}

// 160 threads = 5 warps; warp ww serves templates 2ww (lanes 0-15) and 2ww+1 (lanes 16-31).
// Each lane owns two subgraph rows ra=2*hl, rb=2*hl+1 (hl = lane % 16).
__global__ __launch_bounds__(160, 4)
void ltfgw_kernel(const int* __restrict__ edge_dst,
                  const float* __restrict__ C2g,
                  const float* __restrict__ q0,
                  const float* __restrict__ alpha0,
                  float* __restrict__ out)
{
    __shared__ __align__(16) int      sNodes[S];
    __shared__ __align__(16) unsigned sMask[S];
    __shared__ __align__(16) float    sQ[RPAD];
    __shared__ __align__(16) float    sC2[T][M][RPAD];
    __shared__ __align__(16) float    sC2q[T][RPAD];
    __shared__ __align__(16) float    sP[T][S][RPAD];
    __shared__ __align__(16) float    sW[T][S][RPAD];
    __shared__ __align__(16) float    sV[T][RPAD];
    __shared__ __align__(16) float    sU[T][UPAD];

    const int n    = blockIdx.x;
    const int tid  = threadIdx.x;
    const int ww   = tid >> 5;
    const int lane = tid & 31;
    const int half = lane >> 4;
    const int hl   = lane & 15;
    const int t    = 2 * ww + half;
    const int ra   = 2 * hl;
    const int rb   = ra + 1;
    const bool aa  = (ra < S);   // hl <= 8
    const bool ab  = (rb < S);   // hl <= 7
    const bool vm  = (hl < M);

    if (tid < S) sNodes[tid] = (tid == 0) ? n : edge_dst[n * DEG + tid - 1];
    if (tid == 0) {
        float qq[M];
        float mxq = -1e30f;
#pragma unroll
        for (int m = 0; m < M; m++) { qq[m] = q0[m]; mxq = fmaxf(mxq, qq[m]); }
        float ssum = 0.f;
#pragma unroll
        for (int m = 0; m < M; m++) { qq[m] = __expf(qq[m] - mxq); ssum += qq[m]; }
        float inv = 1.f / ssum;
#pragma unroll
        for (int m = 0; m < M; m++) sQ[m] = qq[m] * inv;
        sQ[10] = 0.f; sQ[11] = 0.f;
    }
    __syncthreads();

    // C1 bitmask (warp 0, full-warp ballot over 17 lanes)
    if (ww == 0) {
        int nodesr[S];
#pragma unroll
        for (int i = 0; i < S; i++) nodesr[i] = sNodes[i];
        unsigned msk0 = 0;
        if (lane < S) {
            int me = nodesr[lane];
#pragma unroll
            for (int kk = 0; kk < DEG / 4; kk++) {
                int4 nb4 = *(const int4*)(edge_dst + me * DEG + kk * 4);
                int nbs[4] = { nb4.x, nb4.y, nb4.z, nb4.w };
#pragma unroll
                for (int j = 0; j < 4; j++) {
#pragma unroll
                    for (int s2 = 0; s2 < S; s2++)
                        if (nbs[j] == nodesr[s2]) msk0 |= 1u << s2;
                }
            }
        }
        unsigned add = 0;
#pragma unroll
        for (int s2 = 0; s2 < S; s2++) {
            unsigned col = __ballot_sync(0xffffffffu, (msk0 >> s2) & 1u);
            if (lane == s2) add = col;
        }
        msk0 |= add & 0x1FFFFu;
        if (lane < S) sMask[lane] = msk0;
    }

    // C2 staging: each (warp, half) stages its own template
    if (vm) {
#pragma unroll
        for (int r = 0; r < M; r++)
            sC2[t][r][hl] = __ldg(C2g + (t * M + r) * M + hl);
    }
    __syncthreads();

    if (vm) {
        float a = 0.f;
#pragma unroll
        for (int b = 0; b < M; b++) {
            float c = sC2[t][hl][b];
            a = fmaf(c * c, sQ[b], a);
        }
        sC2q[t][hl] = a;
    }
    if (hl >= M && hl < RPAD) sC2q[t][hl] = 0.f;

    // Per-row node data
    const int nodea = aa ? sNodes[ra] : 0;
    const int nodeb = ab ? sNodes[rb] : 0;
    const int offa = (nodea * T + t) * RPAD;
    const int offb = (nodeb * T + t) * RPAD;
    const float nxa = aa ? __ldg(g_NX + nodea) : 0.f;
    const float nxb = ab ? __ldg(g_NX + nodeb) : 0.f;
    const u64 nxa2 = pk(nxa, nxa);
    const u64 nxb2 = pk(nxb, nxb);

    const float alpha = 1.f / (1.f + __expf(-__ldg(alpha0 + n)));
    const float a1c = 1.f - alpha;
    const float a2c = 2.f * alpha;
    const u64 a1c2 = pk(a1c, a1c);
    const u64 a2c2 = pk(a2c, a2c);
    const float p = 1.f / 17.f;
    const unsigned mka = aa ? sMask[ra] : 0u;
    const unsigned mkb = ab ? sMask[rb] : 0u;
    const float c1pa = (float)__popc(mka) * (1.f / 17.f);
    const float c1pb = (float)__popc(mkb) * (1.f / 17.f);
    const u64 c1pa2 = pk(c1pa, c1pa);
    const u64 c1pb2 = pk(c1pb, c1pb);
    const float qm = vm ? sQ[hl] : 0.f;

    // plan0 = p (x) q, rows ra and rb
    {
        ulonglong2 qab = *(const ulonglong2*)&sQ[0];
        u64 qc = *(const u64*)&sQ[8];
        u64 p2 = pk(p, p);
        if (aa) {
            ulonglong2 o; o.x = f2mul(p2, qab.x); o.y = f2mul(p2, qab.y);
            *(ulonglong2*)&sP[t][ra][0] = o;
            ulonglong2 qcd = *(const ulonglong2*)&sQ[4];
            ulonglong2 o2; o2.x = f2mul(p2, qcd.x); o2.y = f2mul(p2, qcd.y);
            *(ulonglong2*)&sP[t][ra][4] = o2;
            *(u64*)&sP[t][ra][8] = f2mul(p2, qc);
        }
        if (ab) {
            ulonglong2 qcd = *(const ulonglong2*)&sQ[4];
            ulonglong2 o; o.x = f2mul(p2, qab.x); o.y = f2mul(p2, qab.y);
            *(ulonglong2*)&sP[t][rb][0] = o;
            ulonglong2 o2; o2.x = f2mul(p2, qcd.x); o2.y = f2mul(p2, qcd.y);
            *(ulonglong2*)&sP[t][rb][4] = o2;
            *(u64*)&sP[t][rb][8] = f2mul(p2, qc);
        }
    }
    __syncwarp();

    u64 K2a[5], K2b[5];
    u64 KT2[8]; float KT16 = 0.f;
#pragma unroll
    for (int j = 0; j < 8; j++) KT2[j] = 0;
    u64 v2r[5];
    u64 ta[5], tb[5];
    float ua = 0.f, ub = 0.f;

    for (int outer = 0; outer < N_OUTER; outer++) {
        tens_pair(&sP[t][0][0], &sC2[t][0][0], &sC2q[t][0],
                  mka, mkb, c1pa2, c1pb2, ta, tb);

        // G rows, eps from |G| mean over template, K = exp(-G/eps - mx)
        float Ga[M], Gb[M];
#pragma unroll
        for (int m = 0; m < M; m++) { Ga[m] = 0.f; Gb[m] = 0.f; }
        if (aa) {
            ulonglong2 x01 = __ldg((const ulonglong2*)(g_XFP + offa));
            ulonglong2 x23 = __ldg((const ulonglong2*)(g_XFP + offa + 4));
            u64 x4 = __ldg((const u64*)(g_XFP + offa + 8));
            u64 g;
            g = f2fma(a2c2, ta[0], f2mul(a1c2, f2add(nxa2, x01.x))); upk(Ga[0], Ga[1], g);
            g = f2fma(a2c2, ta[1], f2mul(a1c2, f2add(nxa2, x01.y))); upk(Ga[2], Ga[3], g);
            g = f2fma(a2c2, ta[2], f2mul(a1c2, f2add(nxa2, x23.x))); upk(Ga[4], Ga[5], g);
            g = f2fma(a2c2, ta[3], f2mul(a1c2, f2add(nxa2, x23.y))); upk(Ga[6], Ga[7], g);
            g = f2fma(a2c2, ta[4], f2mul(a1c2, f2add(nxa2, x4)));    upk(Ga[8], Ga[9], g);
        }
        if (ab) {
            ulonglong2 x01 = __ldg((const ulonglong2*)(g_XFP + offb));
            ulonglong2 x23 = __ldg((const ulonglong2*)(g_XFP + offb + 4));
            u64 x4 = __ldg((const u64*)(g_XFP + offb + 8));
            u64 g;
            g = f2fma(a2c2, tb[0], f2mul(a1c2, f2add(nxb2, x01.x))); upk(Gb[0], Gb[1], g);
            g = f2fma(a2c2, tb[1], f2mul(a1c2, f2add(nxb2, x01.y))); upk(Gb[2], Gb[3], g);
            g = f2fma(a2c2, tb[2], f2mul(a1c2, f2add(nxb2, x23.x))); upk(Gb[4], Gb[5], g);
            g = f2fma(a2c2, tb[3], f2mul(a1c2, f2add(nxb2, x23.y))); upk(Gb[6], Gb[7], g);
            g = f2fma(a2c2, tb[4], f2mul(a1c2, f2add(nxb2, x4)));    upk(Gb[8], Gb[9], g);
        }
        float asum = 0.f;
#pragma unroll
        for (int m = 0; m < M; m++) asum += fabsf(Ga[m]) + fabsf(Gb[m]);
#pragma unroll
        for (int o = 8; o; o >>= 1) asum += __shfl_xor_sync(0xffffffffu, asum, o);
        float eps = 0.05f * asum * (1.f / 170.f) + 1e-8f;
        float nie = -__fdividef(1.f, eps);
        float mx = -1e30f;
#pragma unroll
        for (int m = 0; m < M; m++) {
            Ga[m] *= nie; Gb[m] *= nie;
            if (aa) mx = fmaxf(mx, Ga[m]);
            if (ab) mx = fmaxf(mx, Gb[m]);
        }
#pragma unroll
        for (int o = 8; o; o >>= 1) mx = fmaxf(mx, __shfl_xor_sync(0xffffffffu, mx, o));
        float Ksa[M], Ksb[M];
#pragma unroll
        for (int m = 0; m < M; m++) {
            Ksa[m] = aa ? __expf(Ga[m] - mx) : 0.f;
            Ksb[m] = ab ? __expf(Gb[m] - mx) : 0.f;
        }
#pragma unroll
        for (int j = 0; j < 5; j++) {
            K2a[j] = pk(Ksa[2 * j], Ksa[2 * j + 1]);
            K2b[j] = pk(Ksb[2 * j], Ksb[2 * j + 1]);
        }

        // K rows -> sW; v = 1
        if (aa) {
            ulonglong2 o; o.x = K2a[0]; o.y = K2a[1];
            *(ulonglong2*)&sW[t][ra][0] = o;
            ulonglong2 o2; o2.x = K2a[2]; o2.y = K2a[3];
            *(ulonglong2*)&sW[t][ra][4] = o2;
            *(u64*)&sW[t][ra][8] = K2a[4];
        }
        if (ab) {
            ulonglong2 o; o.x = K2b[0]; o.y = K2b[1];
            *(ulonglong2*)&sW[t][rb][0] = o;
            ulonglong2 o2; o2.x = K2b[2]; o2.y = K2b[3];
            *(ulonglong2*)&sW[t][rb][4] = o2;
            *(u64*)&sW[t][rb][8] = K2b[4];
        }
        if (hl < RPAD) sV[t][hl] = (hl < M) ? 1.f : 0.f;
        __syncwarp();
        if (vm) {
            float kt[S];
#pragma unroll
            for (int s2 = 0; s2 < S; s2++) kt[s2] = sW[t][s2][hl];
#pragma unroll
            for (int j = 0; j < 8; j++) KT2[j] = pk(kt[2 * j], kt[2 * j + 1]);
            KT16 = kt[16];
        }
        __syncwarp();

        // Sinkhorn: 16 u-steps, 15 v-steps
        for (int it = 0; it <= N_SINK; it++) {
            ulonglong2 va = *(const ulonglong2*)&sV[t][0];
            ulonglong2 vb = *(const ulonglong2*)&sV[t][4];
            u64 vc = *(const u64*)&sV[t][8];
            v2r[0] = va.x; v2r[1] = va.y; v2r[2] = vb.x; v2r[3] = vb.y; v2r[4] = vc;
            u64 acca = f2mul(K2a[0], v2r[0]);
            acca = f2fma(K2a[1], v2r[1], acca);
            acca = f2fma(K2a[2], v2r[2], acca);
            acca = f2fma(K2a[3], v2r[3], acca);
            acca = f2fma(K2a[4], v2r[4], acca);
            u64 accb = f2mul(K2b[0], v2r[0]);
            accb = f2fma(K2b[1], v2r[1], accb);
            accb = f2fma(K2b[2], v2r[2], accb);
            accb = f2fma(K2b[3], v2r[3], accb);
            accb = f2fma(K2b[4], v2r[4], accb);
            float la, ha, lb, hb;
            upk(la, ha, acca); upk(lb, hb, accb);
            ua = __fdividef(p, fmaxf(la + ha, 1e-35f));
            ub = __fdividef(p, fmaxf(lb + hb, 1e-35f));
            if (it == N_SINK) break;
            if (hl < 9) *(u64*)&sU[t][ra] = pk(ua, ub);
            __syncwarp();
            if (vm) {
                ulonglong2 u01 = *(const ulonglong2*)&sU[t][0];
                ulonglong2 u23 = *(const ulonglong2*)&sU[t][4];
                ulonglong2 u45 = *(const ulonglong2*)&sU[t][8];
                ulonglong2 u67 = *(const ulonglong2*)&sU[t][12];
                float u16 = sU[t][16];
                u64 a2 = f2mul(KT2[0], u01.x);
                a2 = f2fma(KT2[1], u01.y, a2);
                a2 = f2fma(KT2[2], u23.x, a2);
                a2 = f2fma(KT2[3], u23.y, a2);
                a2 = f2fma(KT2[4], u45.x, a2);
                a2 = f2fma(KT2[5], u45.y, a2);
                a2 = f2fma(KT2[6], u67.x, a2);
                a2 = f2fma(KT2[7], u67.y, a2);
                float clo, chi; upk(clo, chi, a2);
                float cs = (clo + chi) + KT16 * u16;
                sV[t][hl] = __fdividef(qm, fmaxf(cs, 1e-35f));
            }
            __syncwarp();
        }

        // plan = u (.) K (.) v
        if (aa) {
            u64 ua2 = pk(ua, ua);
            ulonglong2 o;
            o.x = f2mul(f2mul(ua2, K2a[0]), v2r[0]);
            o.y = f2mul(f2mul(ua2, K2a[1]), v2r[1]);
            *(ulonglong2*)&sP[t][ra][0] = o;
            ulonglong2 o2;
            o2.x = f2mul(f2mul(ua2, K2a[2]), v2r[2]);
            o2.y = f2mul(f2mul(ua2, K2a[3]), v2r[3]);
            *(ulonglong2*)&sP[t][ra][4] = o2;
            *(u64*)&sP[t][ra][8] = f2mul(f2mul(ua2, K2a[4]), v2r[4]);
        }
        if (ab) {
            u64 ub2 = pk(ub, ub);
            ulonglong2 o;
            o.x = f2mul(f2mul(ub2, K2b[0]), v2r[0]);
            o.y = f2mul(f2mul(ub2, K2b[1]), v2r[1]);
            *(ulonglong2*)&sP[t][rb][0] = o;
            ulonglong2 o2;
            o2.x = f2mul(f2mul(ub2, K2b[2]), v2r[2]);
            o2.y = f2mul(f2mul(ub2, K2b[3]), v2r[3]);
            *(ulonglong2*)&sP[t][rb][4] = o2;
            *(u64*)&sP[t][rb][8] = f2mul(f2mul(ub2, K2b[4]), v2r[4]);
        }
        __syncwarp();
    }

    // final tens + contractions
    tens_pair(&sP[t][0][0], &sC2[t][0][0], &sC2q[t][0],
              mka, mkb, c1pa2, c1pb2, ta, tb);

    u64 lin2 = 0, gw2 = 0;
    if (aa) {
        u64 ua2 = pk(ua, ua);
        ulonglong2 x01 = __ldg((const ulonglong2*)(g_XFP + offa));
        ulonglong2 x23 = __ldg((const ulonglong2*)(g_XFP + offa + 4));
        u64 x4 = __ldg((const u64*)(g_XFP + offa + 8));
        u64 xs[5] = { x01.x, x01.y, x23.x, x23.y, x4 };
#pragma unroll
        for (int j = 0; j < 5; j++) {
            u64 pl = f2mul(f2mul(ua2, K2a[j]), v2r[j]);
            lin2 = f2fma(f2add(nxa2, xs[j]), pl, lin2);
            gw2  = f2fma(ta[j], pl, gw2);
        }
    }
    if (ab) {
        u64 ub2 = pk(ub, ub);
        ulonglong2 x01 = __ldg((const ulonglong2*)(g_XFP + offb));
        ulonglong2 x23 = __ldg((const ulonglong2*)(g_XFP + offb + 4));
        u64 x4 = __ldg((const u64*)(g_XFP + offb + 8));
        u64 xs[5] = { x01.x, x01.y, x23.x, x23.y, x4 };
#pragma unroll
        for (int j = 0; j < 5; j++) {
            u64 pl = f2mul(f2mul(ub2, K2b[j]), v2r[j]);
            lin2 = f2fma(f2add(nxb2, xs[j]), pl, lin2);
            gw2  = f2fma(tb[j], pl, gw2);
        }
    }
    float llo, lhi, glo, ghi;
    upk(llo, lhi, lin2);
    upk(glo, ghi, gw2);
    float lin = llo + lhi, gw = glo + ghi;
#pragma unroll
    for (int o = 8; o; o >>= 1) {
        lin += __shfl_xor_sync(0xffffffffu, lin, o);
        gw  += __shfl_xor_sync(0xffffffffu, gw, o);
    }
    if (hl == 0)
        out[n * T + t] = a1c * lin + alpha * gw;
}

extern "C" void kernel_launch(void* const* d_in, const int* in_sizes, int n_in,
                              void* d_out, int out_size)
{
    const float* x      = (const float*)d_in[0];
    const int*   ei     = (const int*)d_in[1];
    const float* C2g    = (const float*)d_in[2];
    const float* F2g    = (const float*)d_in[3];
    const float* q0     = (const float*)d_in[4];
    const float* alpha0 = (const float*)d_in[5];
    float* out = (float*)d_out;

    const int* edge_dst = ei + NNODES * DEG;

    xf2_kernel<<<NNODES / 4, 128>>>(x, F2g);
    ltfgw_kernel<<<NNODES, 160>>>(edge_dst, C2g, q0, alpha0, out);
}